// round 12
// baseline (speedup 1.0000x reference)
#include <cuda_runtime.h>
#include <cuda_fp16.h>
#include <cstdint>
#include <cstddef>

// ---------------- scratch (allocation-free rule: __device__ globals) --------
// Q/K/V intermediates in fp16 (halves DRAM traffic GEMM->epilogue).
__device__ __align__(16) __half g_Q[512 * 768];
__device__ __align__(16) __half g_K[1536 * 768];
__device__ __align__(16) __half g_V[1536 * 768];

// ---------------- helpers ---------------------------------------------------
__device__ __forceinline__ void ldmx4(uint32_t* r, uint32_t addr) {
    asm volatile("ldmatrix.sync.aligned.m8n8.x4.shared.b16 {%0,%1,%2,%3}, [%4];"
                 : "=r"(r[0]), "=r"(r[1]), "=r"(r[2]), "=r"(r[3]) : "r"(addr));
}
__device__ __forceinline__ uint32_t smem_u32(const void* p) {
    uint32_t a;
    asm("{ .reg .u64 t; cvta.to.shared.u64 t, %1; cvt.u32.u64 %0, t; }" : "=r"(a) : "l"(p));
    return a;
}
__device__ __forceinline__ void mma_f16(float* c, const uint32_t* a,
                                        uint32_t b0, uint32_t b1) {
    asm volatile(
        "mma.sync.aligned.m16n8k16.row.col.f32.f16.f16.f32 "
        "{%0,%1,%2,%3}, {%4,%5,%6,%7}, {%8,%9}, {%0,%1,%2,%3};"
        : "+f"(c[0]), "+f"(c[1]), "+f"(c[2]), "+f"(c[3])
        : "r"(a[0]), "r"(a[1]), "r"(a[2]), "r"(a[3]), "r"(b0), "r"(b1));
}
__device__ __forceinline__ void cvt4h_store(char* base, int off, float4 x) {
    uint2 ph;
    ph.x = (uint32_t)__half_as_ushort(__float2half_rn(x.x)) |
           ((uint32_t)__half_as_ushort(__float2half_rn(x.y)) << 16);
    ph.y = (uint32_t)__half_as_ushort(__float2half_rn(x.z)) |
           ((uint32_t)__half_as_ushort(__float2half_rn(x.w)) << 16);
    *(uint2*)(base + off) = ph;
}
__device__ __forceinline__ uint32_t pack_h2(float a, float b) {
    return (uint32_t)__half_as_ushort(__float2half_rn(a)) |
           ((uint32_t)__half_as_ushort(__float2half_rn(b)) << 16);
}
__device__ __forceinline__ float4 ld_half4(const __half* p) {
    const uint2 u = *(const uint2*)p;
    const __half2 h0 = *(const __half2*)&u.x;
    const __half2 h1 = *(const __half2*)&u.y;
    const float2 f0 = __half22float2(h0), f1 = __half22float2(h1);
    return make_float4(f0.x, f0.y, f1.x, f1.y);
}

// ---------------- fused QKV GEMM: fp16 mma.sync m16n8k16 --------------------
// C = A @ W^T + bias, fp16 operands, fp16 output (err ~5e-4 << 1e-3).
// 112 CTAs (single wave), 256 thr, BM=128 x BN=192, K chunked 32 (24 chunks
// -> half the barriers of R11). smem stage 20KB: A[0,8K) 64B rows, B[8K,20K);
// XOR swizzle unit' = u ^ ((row>>1)&3), conflict-free ldmatrix + STS.64.
// 8 warps as 2(m) x 4(n): warp tile 64x48 -> 48 mma per warp per chunk.
#define NCH   24
#define STAGE 20480

__global__ __launch_bounds__(256)
void qkv_gemm_f16(const float* __restrict__ target, const float* __restrict__ cont,
                  const float* __restrict__ wq, const float* __restrict__ wk,
                  const float* __restrict__ wv,
                  const float* __restrict__ bq, const float* __restrict__ bk,
                  const float* __restrict__ bv) {
    __shared__ __align__(16) char smem[2 * STAGE];
    const uint32_t sb = smem_u32(smem);

    const int tid = threadIdx.x, lane = tid & 31, wid = tid >> 5;
    const int blk = blockIdx.x;

    int by, bx, plane;
    const float *srcA, *bias;
    __half* C;
    if (blk < 16)      { int t = blk;      by = t >> 2; bx = t & 3; srcA = target + (size_t)(by * 128) * 768; plane = 0; bias = bq; C = g_Q; }
    else if (blk < 64) { int t = blk - 16; by = t >> 2; bx = t & 3; srcA = cont   + (size_t)(by * 128) * 768; plane = 1; bias = bk; C = g_K; }
    else               { int t = blk - 64; by = t >> 2; bx = t & 3; srcA = cont   + (size_t)(by * 128) * 768; plane = 2; bias = bv; C = g_V; }
    const float* srcB = (plane == 0 ? wq : (plane == 1 ? wk : wv)) + (size_t)(bx * 192) * 768;

    // --- A decode: 1024 fp32-float4 slots per 32-col chunk, 4 per thread ----
    const float* gA[4];
    int dA[4];
#pragma unroll
    for (int i = 0; i < 4; i++) {
        const int id = i * 256 + tid;              // 0..1023
        const int row = id >> 3, seg = id & 7;     // row 0..127, seg 0..7
        gA[i] = srcA + (size_t)row * 768 + seg * 4;
        dA[i] = row * 64 + (((seg >> 1) ^ ((row >> 1) & 3)) * 16) + (seg & 1) * 8;
    }
    // --- B decode: 1536 slots per chunk, 6 per thread ------------------------
    const float* gB[6];
    int dB[6];
#pragma unroll
    for (int i = 0; i < 6; i++) {
        const int id = i * 256 + tid;              // 0..1535
        const int row = id >> 3, seg = id & 7;     // row 0..191
        gB[i] = srcB + (size_t)row * 768 + seg * 4;
        dB[i] = 8192 + row * 64 + (((seg >> 1) ^ ((row >> 1) & 3)) * 16) + (seg & 1) * 8;
    }

    const int warp_m = (wid >> 2) * 64;
    const int warp_n = (wid & 3) * 48;

    const int a_row = lane & 15;
    const int a_sub = (lane >> 4) & 1;
    const int b_row = ((lane >> 4) & 1) * 8 + (lane & 7);
    const int b_sub = (lane >> 3) & 1;

    float acc[4][6][4];
#pragma unroll
    for (int mf = 0; mf < 4; mf++)
#pragma unroll
        for (int j = 0; j < 6; j++)
#pragma unroll
            for (int i = 0; i < 4; i++) acc[mf][j][i] = 0.f;

    float4 rA[4], rB[6];
    // prologue: chunk 0 -> buf 0
#pragma unroll
    for (int i = 0; i < 4; i++) rA[i] = *(const float4*)(gA[i]);
#pragma unroll
    for (int i = 0; i < 6; i++) rB[i] = *(const float4*)(gB[i]);
#pragma unroll
    for (int i = 0; i < 4; i++) cvt4h_store(smem, dA[i], rA[i]);
#pragma unroll
    for (int i = 0; i < 6; i++) cvt4h_store(smem, dB[i], rB[i]);
    __syncthreads();
    // preload chunk 1
#pragma unroll
    for (int i = 0; i < 4; i++) rA[i] = *(const float4*)(gA[i] + 32);
#pragma unroll
    for (int i = 0; i < 6; i++) rB[i] = *(const float4*)(gB[i] + 32);

    for (int c = 0; c < NCH; c++) {
        const int buf = c & 1;
        const uint32_t st = sb + buf * STAGE;

        uint32_t af[4][4], bf[3][4];
        // ---- k-half 0 fragments ----
#pragma unroll
        for (int mf = 0; mf < 4; mf++) {
            const int row = warp_m + mf * 16 + a_row;
            ldmx4(af[mf], st + row * 64 + ((a_sub ^ ((row >> 1) & 3)) * 16));
        }
#pragma unroll
        for (int ng = 0; ng < 3; ng++) {
            const int row = warp_n + ng * 16 + b_row;
            ldmx4(bf[ng], st + 8192 + row * 64 + ((b_sub ^ ((row >> 1) & 3)) * 16));
        }

        const bool more = (c + 1 < NCH);
        if (more) {
            // store chunk c+1 (in regs) into the other buffer
            char* stn = smem + (buf ^ 1) * STAGE;
#pragma unroll
            for (int i = 0; i < 4; i++) cvt4h_store(stn, dA[i], rA[i]);
#pragma unroll
            for (int i = 0; i < 6; i++) cvt4h_store(stn, dB[i], rB[i]);
            // LDG chunk c+2 (clamped); latency hidden under mma below
            const int nc = (c + 2 < NCH) ? (c + 2) : (NCH - 1);
            const size_t off = (size_t)nc * 32;
#pragma unroll
            for (int i = 0; i < 4; i++) rA[i] = *(const float4*)(gA[i] + off);
#pragma unroll
            for (int i = 0; i < 6; i++) rB[i] = *(const float4*)(gB[i] + off);
        }

        // ---- k-half 0 mma ----
#pragma unroll
        for (int mf = 0; mf < 4; mf++)
#pragma unroll
            for (int j = 0; j < 6; j++)
                mma_f16(acc[mf][j], af[mf], bf[j >> 1][(j & 1) * 2], bf[j >> 1][(j & 1) * 2 + 1]);

        // ---- k-half 1 fragments + mma ----
#pragma unroll
        for (int mf = 0; mf < 4; mf++) {
            const int row = warp_m + mf * 16 + a_row;
            ldmx4(af[mf], st + row * 64 + (((2 + a_sub) ^ ((row >> 1) & 3)) * 16));
        }
#pragma unroll
        for (int ng = 0; ng < 3; ng++) {
            const int row = warp_n + ng * 16 + b_row;
            ldmx4(bf[ng], st + 8192 + row * 64 + (((2 + b_sub) ^ ((row >> 1) & 3)) * 16));
        }
#pragma unroll
        for (int mf = 0; mf < 4; mf++)
#pragma unroll
            for (int j = 0; j < 6; j++)
                mma_f16(acc[mf][j], af[mf], bf[j >> 1][(j & 1) * 2], bf[j >> 1][(j & 1) * 2 + 1]);

        __syncthreads();
    }

    // epilogue: bias + store fp16
    const int g4 = lane >> 2, t4 = lane & 3;
#pragma unroll
    for (int mf = 0; mf < 4; mf++) {
        const int row = by * 128 + warp_m + mf * 16 + g4;
#pragma unroll
        for (int j = 0; j < 6; j++) {
            const int col = bx * 192 + warp_n + j * 8 + t4 * 2;
            const float2 bb = *(const float2*)&bias[col];
            *(uint32_t*)&C[(size_t)row * 768 + col] =
                pack_h2(acc[mf][j][0] + bb.x, acc[mf][j][1] + bb.y);
            *(uint32_t*)&C[(size_t)(row + 8) * 768 + col] =
                pack_h2(acc[mf][j][2] + bb.x, acc[mf][j][3] + bb.y);
        }
    }
}

// ---------------- per-batch epilogue: 2 batches per block, fp16 reads -------
__global__ __launch_bounds__(192)
void batch_epilogue(const float* __restrict__ p, const float* __restrict__ hmat,
                    const float* __restrict__ g, float* __restrict__ out) {
    const int b0 = blockIdx.x * 2, tid = threadIdx.x;
    const int lane = tid & 31, wid = tid >> 5;
    __shared__ float wacc[6][24];
    __shared__ float racc[24];

    const int hh = tid * 4;
    float a[2][12];
#pragma unroll
    for (int bb = 0; bb < 2; bb++)
#pragma unroll
        for (int i = 0; i < 12; i++) a[bb][i] = 0.f;

    float4 v4[2][3], q4[2];
    q4[0] = ld_half4(&g_Q[(size_t)b0 * 768 + hh]);
    q4[1] = ld_half4(&g_Q[(size_t)(b0 + 1) * 768 + hh]);
#pragma unroll
    for (int mp = 0; mp < 3; mp++) {
        const float4 pm = *(const float4*)&p[mp * 768 + hh];
        const float4* hrp = (const float4*)&hmat[((size_t)(mp * 768 + hh)) * 3];
        const float4 f0 = hrp[0], f1 = hrp[1], f2 = hrp[2];
        const float hr[12] = {f0.x, f0.y, f0.z, f0.w, f1.x, f1.y,
                              f1.z, f1.w, f2.x, f2.y, f2.z, f2.w};
#pragma unroll
        for (int bb = 0; bb < 2; bb++) {
            const int b = b0 + bb;
            const float4 k4 = ld_half4(&g_K[((size_t)b * 3 + mp) * 768 + hh]);
            v4[bb][mp]      = ld_half4(&g_V[((size_t)b * 3 + mp) * 768 + hh]);
            const float4 q = q4[bb];
            a[bb][mp] += pm.x * q.x + pm.y * q.y + pm.z * q.z + pm.w * q.w;
            const float t[4] = {q.x * k4.x, q.y * k4.y, q.z * k4.z, q.w * k4.w};
#pragma unroll
            for (int e = 0; e < 4; e++) {
                a[bb][3] += t[e] * hr[e * 3 + 0];
                a[bb][4] += t[e] * hr[e * 3 + 1];
                a[bb][5] += t[e] * hr[e * 3 + 2];
            }
        }
    }
#pragma unroll
    for (int bb = 0; bb < 2; bb++) {
        const float4 v0 = v4[bb][0], v1 = v4[bb][1], v2 = v4[bb][2];
        a[bb][6]  += v0.x*v0.x + v0.y*v0.y + v0.z*v0.z + v0.w*v0.w;
        a[bb][7]  += v0.x*v1.x + v0.y*v1.y + v0.z*v1.z + v0.w*v1.w;
        a[bb][8]  += v0.x*v2.x + v0.y*v2.y + v0.z*v2.z + v0.w*v2.w;
        a[bb][9]  += v1.x*v1.x + v1.y*v1.y + v1.z*v1.z + v1.w*v1.w;
        a[bb][10] += v1.x*v2.x + v1.y*v2.y + v1.z*v2.z + v1.w*v2.w;
        a[bb][11] += v2.x*v2.x + v2.y*v2.y + v2.z*v2.z + v2.w*v2.w;
    }

#pragma unroll
    for (int bb = 0; bb < 2; bb++)
#pragma unroll
        for (int i = 0; i < 12; i++) {
            float v = a[bb][i];
#pragma unroll
            for (int off = 16; off; off >>= 1)
                v += __shfl_down_sync(0xffffffffu, v, off);
            if (lane == 0) wacc[wid][bb * 12 + i] = v;
        }
    __syncthreads();
    if (tid < 24) {
        float s = 0.f;
#pragma unroll
        for (int w = 0; w < 6; w++) s += wacc[w][tid];
        racc[tid] = s;
    }
    __syncthreads();

    const float4 g0 = *(const float4*)&g[hh];
    const float4 g1 = *(const float4*)&g[768 + hh];
    const float4 g2 = *(const float4*)&g[1536 + hh];
#pragma unroll
    for (int bb = 0; bb < 2; bb++) {
        const float* rc = &racc[bb * 12];
        const float ker0 = rc[0] + rc[3];
        const float ker1 = rc[1] + rc[4];
        const float ker2 = rc[2] + rc[5];
        const float c0 = ker0 * rc[6] + ker1 * rc[7]  + ker2 * rc[8];
        const float c1 = ker0 * rc[7] + ker1 * rc[9]  + ker2 * rc[10];
        const float c2 = ker0 * rc[8] + ker1 * rc[10] + ker2 * rc[11];
        const float4 v0 = v4[bb][0], v1 = v4[bb][1], v2 = v4[bb][2];
        float4 o;
        o.x = ker0*v0.x + ker1*v1.x + ker2*v2.x + c0*g0.x + c1*g1.x + c2*g2.x;
        o.y = ker0*v0.y + ker1*v1.y + ker2*v2.y + c0*g0.y + c1*g1.y + c2*g2.y;
        o.z = ker0*v0.z + ker1*v1.z + ker2*v2.z + c0*g0.z + c1*g1.z + c2*g2.z;
        o.w = ker0*v0.w + ker1*v1.w + ker2*v2.w + c0*g0.w + c1*g1.w + c2*g2.w;
        *(float4*)&out[(size_t)(b0 + bb) * 768 + hh] = o;
    }
}

// ---------------- launch -----------------------------------------------------
extern "C" void kernel_launch(void* const* d_in, const int* in_sizes, int n_in,
                              void* d_out, int out_size) {
    const float* target = (const float*)d_in[0];
    const float* cont   = (const float*)d_in[1];
    const float* Wq     = (const float*)d_in[2];
    const float* bq     = (const float*)d_in[3];
    const float* Wk     = (const float*)d_in[4];
    const float* bk     = (const float*)d_in[5];
    const float* Wv     = (const float*)d_in[6];
    const float* bv     = (const float*)d_in[7];
    const float* p      = (const float*)d_in[8];
    const float* hmat   = (const float*)d_in[9];
    const float* g      = (const float*)d_in[10];
    float* out = (float*)d_out;

    qkv_gemm_f16<<<112, 256>>>(target, cont, Wq, Wk, Wv, bq, bk, bv);
    batch_epilogue<<<256, 192>>>(p, hmat, g, out);
}

// round 13
// speedup vs baseline: 1.0009x; 1.0009x over previous
#include <cuda_runtime.h>
#include <cuda_fp16.h>
#include <cstdint>
#include <cstddef>

// ---------------- scratch (allocation-free rule: __device__ globals) --------
// Q/K/V intermediates in fp16 (halves GEMM store + epilogue load traffic).
__device__ __align__(16) __half g_Q[512 * 768];
__device__ __align__(16) __half g_K[1536 * 768];
__device__ __align__(16) __half g_V[1536 * 768];

// ---------------- helpers ---------------------------------------------------
__device__ __forceinline__ void ldmx4(uint32_t* r, uint32_t addr) {
    asm volatile("ldmatrix.sync.aligned.m8n8.x4.shared.b16 {%0,%1,%2,%3}, [%4];"
                 : "=r"(r[0]), "=r"(r[1]), "=r"(r[2]), "=r"(r[3]) : "r"(addr));
}
__device__ __forceinline__ uint32_t smem_u32(const void* p) {
    uint32_t a;
    asm("{ .reg .u64 t; cvta.to.shared.u64 t, %1; cvt.u32.u64 %0, t; }" : "=r"(a) : "l"(p));
    return a;
}
__device__ __forceinline__ void mma_f16(float* c, const uint32_t* a,
                                        uint32_t b0, uint32_t b1) {
    asm volatile(
        "mma.sync.aligned.m16n8k16.row.col.f32.f16.f16.f32 "
        "{%0,%1,%2,%3}, {%4,%5,%6,%7}, {%8,%9}, {%0,%1,%2,%3};"
        : "+f"(c[0]), "+f"(c[1]), "+f"(c[2]), "+f"(c[3])
        : "r"(a[0]), "r"(a[1]), "r"(a[2]), "r"(a[3]), "r"(b0), "r"(b1));
}
__device__ __forceinline__ void cvt4h_store(char* base, int off, float4 x) {
    uint2 ph;
    ph.x = (uint32_t)__half_as_ushort(__float2half_rn(x.x)) |
           ((uint32_t)__half_as_ushort(__float2half_rn(x.y)) << 16);
    ph.y = (uint32_t)__half_as_ushort(__float2half_rn(x.z)) |
           ((uint32_t)__half_as_ushort(__float2half_rn(x.w)) << 16);
    *(uint2*)(base + off) = ph;
}
__device__ __forceinline__ uint32_t pack_h2(float a, float b) {
    return (uint32_t)__half_as_ushort(__float2half_rn(a)) |
           ((uint32_t)__half_as_ushort(__float2half_rn(b)) << 16);
}
__device__ __forceinline__ float2 ld_half2f(const __half* p) {
    return __half22float2(*(const __half2*)p);
}

// ---------------- fused QKV GEMM: fp16 mma.sync m16n8k16 (R11 skeleton) -----
// C = A @ W^T + bias, fp16 operands, fp16 output.
// 112 CTAs (single wave), 256 thr, BM=128 x BN=192, K chunked 16 (48 chunks).
//   [0,16)=Q, [16,64)=K, [64,112)=V.
// smem stage 10KB: A[0,4K) B[4K,10K), 32B swizzled rows; double buffered.
// 8 warps as 2(m) x 4(n): warp tile 64x48 -> 24 mma per warp per chunk.
#define NCH   48
#define STAGE 10240

__global__ __launch_bounds__(256)
void qkv_gemm_f16(const float* __restrict__ target, const float* __restrict__ cont,
                  const float* __restrict__ wq, const float* __restrict__ wk,
                  const float* __restrict__ wv,
                  const float* __restrict__ bq, const float* __restrict__ bk,
                  const float* __restrict__ bv) {
    __shared__ __align__(16) char smem[2 * STAGE];
    const uint32_t sb = smem_u32(smem);

    const int tid = threadIdx.x, lane = tid & 31, wid = tid >> 5;
    const int blk = blockIdx.x;

    int by, bx, plane;
    const float *srcA, *bias;
    __half* C;
    if (blk < 16)      { int t = blk;      by = t >> 2; bx = t & 3; srcA = target + (size_t)(by * 128) * 768; plane = 0; bias = bq; C = g_Q; }
    else if (blk < 64) { int t = blk - 16; by = t >> 2; bx = t & 3; srcA = cont   + (size_t)(by * 128) * 768; plane = 1; bias = bk; C = g_K; }
    else               { int t = blk - 64; by = t >> 2; bx = t & 3; srcA = cont   + (size_t)(by * 128) * 768; plane = 2; bias = bv; C = g_V; }
    const float* srcB = (plane == 0 ? wq : (plane == 1 ? wk : wv)) + (size_t)(bx * 192) * 768;

    // --- A decode: 512 fp32-float4 slots per chunk, 2 per thread -------------
    const float* gA[2];
    int dA[2];
#pragma unroll
    for (int i = 0; i < 2; i++) {
        const int id = i * 256 + tid;
        const int row = id >> 2, seg = id & 3;
        gA[i] = srcA + (size_t)row * 768 + seg * 4;
        dA[i] = row * 32 + (((seg >> 1) ^ (row >> 2)) & 1) * 16 + (seg & 1) * 8;
    }
    // --- B decode: 768 fp32-float4 slots per chunk, 3 per thread -------------
    const float* gB[3];
    int dB[3];
#pragma unroll
    for (int i = 0; i < 3; i++) {
        const int id = i * 256 + tid;               // 0..767
        const int row = id >> 2, seg = id & 3;      // row 0..191
        gB[i] = srcB + (size_t)row * 768 + seg * 4;
        dB[i] = 4096 + row * 32 + (((seg >> 1) ^ (row >> 2)) & 1) * 16 + (seg & 1) * 8;
    }

    const int warp_m = (wid >> 2) * 64;
    const int warp_n = (wid & 3) * 48;

    const int a_row = lane & 15;
    const int a_sub = (lane >> 4) & 1;
    const int b_row = ((lane >> 4) & 1) * 8 + (lane & 7);
    const int b_sub = (lane >> 3) & 1;

    float acc[4][6][4];
#pragma unroll
    for (int mf = 0; mf < 4; mf++)
#pragma unroll
        for (int j = 0; j < 6; j++)
#pragma unroll
            for (int i = 0; i < 4; i++) acc[mf][j][i] = 0.f;

    float4 rA[2], rB[3];
    // prologue: chunk 0 -> buf 0
#pragma unroll
    for (int i = 0; i < 2; i++) rA[i] = *(const float4*)(gA[i]);
#pragma unroll
    for (int i = 0; i < 3; i++) rB[i] = *(const float4*)(gB[i]);
#pragma unroll
    for (int i = 0; i < 2; i++) cvt4h_store(smem, dA[i], rA[i]);
#pragma unroll
    for (int i = 0; i < 3; i++) cvt4h_store(smem, dB[i], rB[i]);
    __syncthreads();
    // preload chunk 1
#pragma unroll
    for (int i = 0; i < 2; i++) rA[i] = *(const float4*)(gA[i] + 16);
#pragma unroll
    for (int i = 0; i < 3; i++) rB[i] = *(const float4*)(gB[i] + 16);

    for (int c = 0; c < NCH; c++) {
        const int buf = c & 1;
        const uint32_t st = sb + buf * STAGE;

        uint32_t af[4][4], bf[3][4];
#pragma unroll
        for (int mf = 0; mf < 4; mf++) {
            const int row = warp_m + mf * 16 + a_row;
            ldmx4(af[mf], st + row * 32 + ((a_sub ^ (row >> 2)) & 1) * 16);
        }
#pragma unroll
        for (int ng = 0; ng < 3; ng++) {
            const int row = warp_n + ng * 16 + b_row;
            ldmx4(bf[ng], st + 4096 + row * 32 + ((b_sub ^ (row >> 2)) & 1) * 16);
        }

        const bool more = (c + 1 < NCH);
        if (more) {
            char* stn = smem + (buf ^ 1) * STAGE;
#pragma unroll
            for (int i = 0; i < 2; i++) cvt4h_store(stn, dA[i], rA[i]);
#pragma unroll
            for (int i = 0; i < 3; i++) cvt4h_store(stn, dB[i], rB[i]);
            const int nc = (c + 2 < NCH) ? (c + 2) : (NCH - 1);
            const size_t off = (size_t)nc * 16;
#pragma unroll
            for (int i = 0; i < 2; i++) rA[i] = *(const float4*)(gA[i] + off);
#pragma unroll
            for (int i = 0; i < 3; i++) rB[i] = *(const float4*)(gB[i] + off);
        }

#pragma unroll
        for (int mf = 0; mf < 4; mf++)
#pragma unroll
            for (int j = 0; j < 6; j++)
                mma_f16(acc[mf][j], af[mf], bf[j >> 1][(j & 1) * 2], bf[j >> 1][(j & 1) * 2 + 1]);

        __syncthreads();
    }

    // epilogue: bias + store fp16
    const int g4 = lane >> 2, t4 = lane & 3;
#pragma unroll
    for (int mf = 0; mf < 4; mf++) {
        const int row = by * 128 + warp_m + mf * 16 + g4;
#pragma unroll
        for (int j = 0; j < 6; j++) {
            const int col = bx * 192 + warp_n + j * 8 + t4 * 2;
            const float2 bb = *(const float2*)&bias[col];
            *(uint32_t*)&C[(size_t)row * 768 + col] =
                pack_h2(acc[mf][j][0] + bb.x, acc[mf][j][1] + bb.y);
            *(uint32_t*)&C[(size_t)(row + 8) * 768 + col] =
                pack_h2(acc[mf][j][2] + bb.x, acc[mf][j][3] + bb.y);
        }
    }
}

// ---------------- per-batch epilogue: 512 blocks x 384 thr (2 els/thread) ---
// High-occupancy latency hiding: ~65% occ vs 16% in R12.
__global__ __launch_bounds__(384)
void batch_epilogue(const float* __restrict__ p, const float* __restrict__ hmat,
                    const float* __restrict__ g, float* __restrict__ out) {
    const int b = blockIdx.x, tid = threadIdx.x;
    const int lane = tid & 31, wid = tid >> 5;   // 12 warps
    __shared__ float wacc[12][12];
    __shared__ float racc[12];

    const int hh = tid * 2;
    float a[12];
#pragma unroll
    for (int i = 0; i < 12; i++) a[i] = 0.f;

    float2 v2[3];
    const float2 q2 = ld_half2f(&g_Q[(size_t)b * 768 + hh]);
#pragma unroll
    for (int mp = 0; mp < 3; mp++) {
        const float2 k2 = ld_half2f(&g_K[((size_t)b * 3 + mp) * 768 + hh]);
        v2[mp]          = ld_half2f(&g_V[((size_t)b * 3 + mp) * 768 + hh]);
        const float2 pm = *(const float2*)&p[mp * 768 + hh];
        a[mp] += pm.x * q2.x + pm.y * q2.y;

        const float2* hrp = (const float2*)&hmat[((size_t)(mp * 768 + hh)) * 3];
        const float2 f0 = hrp[0], f1 = hrp[1], f2 = hrp[2];
        const float hr[6] = {f0.x, f0.y, f1.x, f1.y, f2.x, f2.y};
        const float t0 = q2.x * k2.x, t1 = q2.y * k2.y;
        a[3] += t0 * hr[0] + t1 * hr[3];
        a[4] += t0 * hr[1] + t1 * hr[4];
        a[5] += t0 * hr[2] + t1 * hr[5];
    }
    const float2 v0 = v2[0], v1 = v2[1], vv2 = v2[2];
    a[6]  += v0.x*v0.x  + v0.y*v0.y;
    a[7]  += v0.x*v1.x  + v0.y*v1.y;
    a[8]  += v0.x*vv2.x + v0.y*vv2.y;
    a[9]  += v1.x*v1.x  + v1.y*v1.y;
    a[10] += v1.x*vv2.x + v1.y*vv2.y;
    a[11] += vv2.x*vv2.x + vv2.y*vv2.y;

#pragma unroll
    for (int i = 0; i < 12; i++) {
        float v = a[i];
#pragma unroll
        for (int off = 16; off; off >>= 1)
            v += __shfl_down_sync(0xffffffffu, v, off);
        if (lane == 0) wacc[wid][i] = v;
    }
    __syncthreads();
    if (tid < 12) {
        float s = 0.f;
#pragma unroll
        for (int w = 0; w < 12; w++) s += wacc[w][tid];
        racc[tid] = s;
    }
    __syncthreads();

    const float ker0 = racc[0] + racc[3];
    const float ker1 = racc[1] + racc[4];
    const float ker2 = racc[2] + racc[5];
    const float c0 = ker0 * racc[6] + ker1 * racc[7]  + ker2 * racc[8];
    const float c1 = ker0 * racc[7] + ker1 * racc[9]  + ker2 * racc[10];
    const float c2 = ker0 * racc[8] + ker1 * racc[10] + ker2 * racc[11];
    const float2 g0 = *(const float2*)&g[hh];
    const float2 g1 = *(const float2*)&g[768 + hh];
    const float2 g2 = *(const float2*)&g[1536 + hh];
    float2 o;
    o.x = ker0*v0.x + ker1*v1.x + ker2*vv2.x + c0*g0.x + c1*g1.x + c2*g2.x;
    o.y = ker0*v0.y + ker1*v1.y + ker2*vv2.y + c0*g0.y + c1*g1.y + c2*g2.y;
    *(float2*)&out[(size_t)b * 768 + hh] = o;
}

// ---------------- launch -----------------------------------------------------
extern "C" void kernel_launch(void* const* d_in, const int* in_sizes, int n_in,
                              void* d_out, int out_size) {
    const float* target = (const float*)d_in[0];
    const float* cont   = (const float*)d_in[1];
    const float* Wq     = (const float*)d_in[2];
    const float* bq     = (const float*)d_in[3];
    const float* Wk     = (const float*)d_in[4];
    const float* bk     = (const float*)d_in[5];
    const float* Wv     = (const float*)d_in[6];
    const float* bv     = (const float*)d_in[7];
    const float* p      = (const float*)d_in[8];
    const float* hmat   = (const float*)d_in[9];
    const float* g      = (const float*)d_in[10];
    float* out = (float*)d_out;

    qkv_gemm_f16<<<112, 256>>>(target, cont, Wq, Wk, Wv, bq, bk, bv);
    batch_epilogue<<<512, 384>>>(p, hmat, g, out);
}